// round 1
// baseline (speedup 1.0000x reference)
#include <cuda_runtime.h>
#include <math.h>

#define TPB 256

namespace swin {
constexpr int Bc = 32, Hh = 56, Wc = 56, Cc = 192;
constexpr int WSc = 7, SSc = 3, NHc = 6, Nn = 49, HDc = 32;
constexpr int NWIN = 64;                 // windows per image (8x8)
constexpr int NBLK = Bc * NWIN;          // 2048 attention blocks
constexpr int Tt = Bc * Hh * Wc;         // 100352 tokens
constexpr int HID = 768;
constexpr float SCALE = 0.17677669529663689f;   // 1/sqrt(32)
constexpr float EPSc = 1e-5f;

// padded strides (bank-conflict avoidance)
constexpr int QS  = 193;   // q/k/v row stride (odd -> conflict-free key gather)
constexpr int SCS = 50;    // score row stride
constexpr int WTS = 34;    // weight tile row stride (even for 8B loads, 34%32=2)

// ---- kernel-1 shared memory layout (float words) ----
constexpr int OFF_XW  = 0;                     // 49*192  LN'd window / attn out
constexpr int OFF_Q   = OFF_XW + Nn * Cc;      // 49*193
constexpr int OFF_K   = OFF_Q + Nn * QS;
constexpr int OFF_V   = OFF_K + Nn * QS;
constexpr int OFF_SC  = OFF_V + Nn * QS;       // 49*50
constexpr int OFF_RPB = OFF_SC + Nn * SCS;     // 169*6
constexpr int OFF_LAB = OFF_RPB + 169 * 6;     // 49 ints
constexpr int OFF_WT1 = OFF_LAB + Nn;          // 64*34 (even offset: 41292)
constexpr int SMEM1_W = OFF_WT1 + 64 * WTS;    // 43468 words = 173872 B

// ---- kernel-2 shared memory layout ----
constexpr int OFF_HT  = 0;                     // 32*192 residual
constexpr int OFF_LN2 = OFF_HT + 32 * Cc;      // 32*192 normalized
constexpr int OFF_A1  = OFF_LN2 + 32 * Cc;     // 32*768 gelu(fc1)
constexpr int OFF_WT2 = OFF_A1 + 32 * HID;     // 64*34
constexpr int SMEM2_W = OFF_WT2 + 64 * WTS;    // 39040 words = 156160 B
}  // namespace swin

using namespace swin;

// intermediate h = x + attn_out (scratch, static device allocation)
__device__ float g_h[(size_t)Tt * Cc];

// ---------- packed f32x2 FMA helpers (sm_103a FFMA2) ----------
__device__ __forceinline__ void fma2(unsigned long long& d,
                                     unsigned long long a,
                                     unsigned long long b) {
    asm("fma.rn.f32x2 %0, %1, %2, %0;" : "+l"(d) : "l"(a), "l"(b));
}
__device__ __forceinline__ float sum2(unsigned long long a) {
    float lo = __uint_as_float((unsigned int)a);
    float hi = __uint_as_float((unsigned int)(a >> 32));
    return lo + hi;
}

// =====================================================================
// Kernel 1: per-window  LN1 -> qkv -> attention -> proj -> +residual
// =====================================================================
__global__ void __launch_bounds__(TPB, 1)
attn_kernel(const float* __restrict__ x,
            const float* __restrict__ n1g, const float* __restrict__ n1b,
            const float* __restrict__ qkvw, const float* __restrict__ qkvb,
            const float* __restrict__ projw, const float* __restrict__ projb,
            const float* __restrict__ rpbt) {
    extern __shared__ float sm[];
    float* xw  = sm + OFF_XW;
    float* q   = sm + OFF_Q;
    float* ks  = sm + OFF_K;
    float* v   = sm + OFF_V;
    float* sc  = sm + OFF_SC;
    float* rpb = sm + OFF_RPB;
    int*   lab = (int*)(sm + OFF_LAB);
    float* wt  = sm + OFF_WT1;

    const int tid = threadIdx.x;
    const int wp = tid >> 5, lane = tid & 31;
    const int bw  = blockIdx.x;
    const int img = bw >> 6;
    const int win = bw & 63;
    const int wr = win >> 3, wcw = win & 7;

    // ---- preload relative position bias table + region labels ----
    for (int i = tid; i < 169 * 6; i += TPB) rpb[i] = rpbt[i];
    if (tid < Nn) {
        int r = tid / 7, c = tid % 7;
        int y = wr * 7 + r, xx = wcw * 7 + c;
        int ry = (y  < 49) ? 0 : (y  < 53 ? 1 : 2);
        int rx = (xx < 49) ? 0 : (xx < 53 ? 1 : 2);
        lab[tid] = ry * 3 + rx;
    }

    // ---- fused shifted-window gather + LayerNorm1 (one warp per token) ----
    for (int n = wp; n < Nn; n += 8) {
        int r = n / 7, c = n % 7;
        int sy = (wr * 7 + r + SSc) % Hh;
        int sx = (wcw * 7 + c + SSc) % Wc;
        const float* xr = x + (size_t)(img * 3136 + sy * 56 + sx) * Cc;
        float vals[6];
        float s = 0.f;
        #pragma unroll
        for (int j = 0; j < 6; j++) { vals[j] = xr[lane + 32 * j]; s += vals[j]; }
        #pragma unroll
        for (int o = 16; o; o >>= 1) s += __shfl_xor_sync(~0u, s, o);
        float mu = s * (1.f / 192.f);
        float s2 = 0.f;
        #pragma unroll
        for (int j = 0; j < 6; j++) { float d = vals[j] - mu; s2 += d * d; }
        #pragma unroll
        for (int o = 16; o; o >>= 1) s2 += __shfl_xor_sync(~0u, s2, o);
        float rs = rsqrtf(s2 * (1.f / 192.f) + EPSc);
        #pragma unroll
        for (int j = 0; j < 6; j++) {
            int cc = lane + 32 * j;
            xw[n * Cc + cc] = (vals[j] - mu) * rs * n1g[cc] + n1b[cc];
        }
    }
    __syncthreads();

    const int gc = tid & 63, rg = tid >> 6;   // column-in-tile, row group

    // ---- qkv GEMM: [49,192] @ [192,576]^T, f32x2 inner product ----
    for (int j0 = 0; j0 < 576; j0 += 64) {
        unsigned long long acc[13];
        #pragma unroll
        for (int rr = 0; rr < 13; rr++) acc[rr] = 0ull;
        for (int k0 = 0; k0 < Cc; k0 += 32) {
            __syncthreads();
            #pragma unroll
            for (int l = 0; l < 8; l++) {
                int e = tid + l * TPB;
                int cw = e >> 5, kw = e & 31;
                wt[cw * WTS + kw] = qkvw[(j0 + cw) * Cc + k0 + kw];
            }
            __syncthreads();
            unsigned long long wv[16];
            const unsigned long long* wrow = (const unsigned long long*)(wt + gc * WTS);
            #pragma unroll
            for (int p = 0; p < 16; p++) wv[p] = wrow[p];
            #pragma unroll
            for (int rr = 0; rr < 13; rr++) {
                int n = rg + (rr << 2);
                if (n < Nn) {
                    const unsigned long long* ar =
                        (const unsigned long long*)(xw + n * Cc + k0);
                    #pragma unroll
                    for (int p = 0; p < 16; p++) fma2(acc[rr], ar[p], wv[p]);
                }
            }
        }
        int j = j0 + gc;
        float bias = qkvb[j];
        float* dst; int jj; float scl = 1.f;
        if (j < 192)      { dst = q;  jj = j;       scl = SCALE; }
        else if (j < 384) { dst = ks; jj = j - 192; }
        else              { dst = v;  jj = j - 384; }
        #pragma unroll
        for (int rr = 0; rr < 13; rr++) {
            int n = rg + (rr << 2);
            if (n < Nn) dst[n * QS + jj] = (sum2(acc[rr]) + bias) * scl;
        }
    }
    __syncthreads();

    // ---- attention per head: scores (+bias +mask) -> softmax -> P@V ----
    for (int h = 0; h < NHc; h++) {
        for (int i = wp; i < Nn; i += 8) {
            const float* qi = q + i * QS + h * HDc;
            float qreg[32];
            #pragma unroll
            for (int d = 0; d < 32; d++) qreg[d] = qi[d];
            int ri = i / 7, ci = i % 7;
            int li = lab[i];

            float s0, s1;
            {
                int j = lane;  // always < 49
                const float* kj = ks + j * QS + h * HDc;
                float a = 0.f;
                #pragma unroll
                for (int d = 0; d < 32; d++) a += qreg[d] * kj[d];
                int rj = j / 7, cj = j % 7;
                a += rpb[((ri - rj + 6) * 13 + (ci - cj + 6)) * 6 + h];
                if (lab[j] != li) a -= 100.f;
                s0 = a;
            }
            if (lane < 17) {
                int j = lane + 32;
                const float* kj = ks + j * QS + h * HDc;
                float a = 0.f;
                #pragma unroll
                for (int d = 0; d < 32; d++) a += qreg[d] * kj[d];
                int rj = j / 7, cj = j % 7;
                a += rpb[((ri - rj + 6) * 13 + (ci - cj + 6)) * 6 + h];
                if (lab[j] != li) a -= 100.f;
                s1 = a;
            } else {
                s1 = __int_as_float(0xff800000);  // -inf
            }
            float m = fmaxf(s0, s1);
            #pragma unroll
            for (int o = 16; o; o >>= 1) m = fmaxf(m, __shfl_xor_sync(~0u, m, o));
            float e0 = __expf(s0 - m);
            float e1 = (lane < 17) ? __expf(s1 - m) : 0.f;
            float ssum = e0 + e1;
            #pragma unroll
            for (int o = 16; o; o >>= 1) ssum += __shfl_xor_sync(~0u, ssum, o);
            float inv = __frcp_rn(ssum);
            sc[i * SCS + lane] = e0 * inv;
            if (lane < 17) sc[i * SCS + lane + 32] = e1 * inv;
        }
        __syncthreads();
        // out[i, h*32+d] = sum_j P[i,j] * V[j, h*32+d]  (reuse xw as out buffer)
        for (int e = tid; e < Nn * HDc; e += TPB) {
            int i = e >> 5, d = e & 31;
            const float* vp = v + h * HDc + d;
            const float* pp = sc + i * SCS;
            float a = 0.f;
            #pragma unroll
            for (int j = 0; j < Nn; j++) a += pp[j] * vp[j * QS];
            xw[i * Cc + h * HDc + d] = a;
        }
        __syncthreads();
    }

    // ---- proj GEMM + window-reverse + roll-back + residual write ----
    for (int j0 = 0; j0 < Cc; j0 += 64) {
        unsigned long long acc[13];
        #pragma unroll
        for (int rr = 0; rr < 13; rr++) acc[rr] = 0ull;
        for (int k0 = 0; k0 < Cc; k0 += 32) {
            __syncthreads();
            #pragma unroll
            for (int l = 0; l < 8; l++) {
                int e = tid + l * TPB;
                int cw = e >> 5, kw = e & 31;
                wt[cw * WTS + kw] = projw[(j0 + cw) * Cc + k0 + kw];
            }
            __syncthreads();
            unsigned long long wv[16];
            const unsigned long long* wrow = (const unsigned long long*)(wt + gc * WTS);
            #pragma unroll
            for (int p = 0; p < 16; p++) wv[p] = wrow[p];
            #pragma unroll
            for (int rr = 0; rr < 13; rr++) {
                int n = rg + (rr << 2);
                if (n < Nn) {
                    const unsigned long long* ar =
                        (const unsigned long long*)(xw + n * Cc + k0);
                    #pragma unroll
                    for (int p = 0; p < 16; p++) fma2(acc[rr], ar[p], wv[p]);
                }
            }
        }
        int j = j0 + gc;
        float b = projb[j];
        #pragma unroll
        for (int rr = 0; rr < 13; rr++) {
            int n = rg + (rr << 2);
            if (n < Nn) {
                int r = n / 7, c = n % 7;
                int sy = (wr * 7 + r + SSc) % Hh;
                int sx = (wcw * 7 + c + SSc) % Wc;
                size_t t = (size_t)(img * 3136 + sy * 56 + sx);
                g_h[t * Cc + j] = x[t * Cc + j] + sum2(acc[rr]) + b;
            }
        }
    }
}

// =====================================================================
// Kernel 2: per-32-token tile  LN2 -> fc1 -> GELU -> fc2 -> +residual
// =====================================================================
__global__ void __launch_bounds__(TPB, 1)
mlp_kernel(const float* __restrict__ n2g, const float* __restrict__ n2b,
           const float* __restrict__ fc1w, const float* __restrict__ fc1b,
           const float* __restrict__ fc2w, const float* __restrict__ fc2b,
           float* __restrict__ out) {
    extern __shared__ float sm[];
    float* ht  = sm + OFF_HT;
    float* lnb = sm + OFF_LN2;
    float* a1  = sm + OFF_A1;
    float* wt  = sm + OFF_WT2;

    const int tid = threadIdx.x;
    const int wp = tid >> 5, lane = tid & 31;
    const int t0 = blockIdx.x * 32;

    // ---- load + LayerNorm2 (warp per token) ----
    for (int n = wp; n < 32; n += 8) {
        const float* hr = g_h + (size_t)(t0 + n) * Cc;
        float vals[6];
        float s = 0.f;
        #pragma unroll
        for (int j = 0; j < 6; j++) { vals[j] = hr[lane + 32 * j]; s += vals[j]; }
        #pragma unroll
        for (int o = 16; o; o >>= 1) s += __shfl_xor_sync(~0u, s, o);
        float mu = s * (1.f / 192.f);
        float s2 = 0.f;
        #pragma unroll
        for (int j = 0; j < 6; j++) { float d = vals[j] - mu; s2 += d * d; }
        #pragma unroll
        for (int o = 16; o; o >>= 1) s2 += __shfl_xor_sync(~0u, s2, o);
        float rs = rsqrtf(s2 * (1.f / 192.f) + EPSc);
        #pragma unroll
        for (int j = 0; j < 6; j++) {
            int cc = lane + 32 * j;
            ht[n * Cc + cc]  = vals[j];
            lnb[n * Cc + cc] = (vals[j] - mu) * rs * n2g[cc] + n2b[cc];
        }
    }
    __syncthreads();

    const int gc = tid & 63, rg = tid >> 6;

    // ---- fc1: [32,192] @ [192,768]^T + b -> exact GELU -> a1 ----
    for (int j0 = 0; j0 < HID; j0 += 64) {
        unsigned long long acc[8];
        #pragma unroll
        for (int rr = 0; rr < 8; rr++) acc[rr] = 0ull;
        for (int k0 = 0; k0 < Cc; k0 += 32) {
            __syncthreads();
            #pragma unroll
            for (int l = 0; l < 8; l++) {
                int e = tid + l * TPB;
                int cw = e >> 5, kw = e & 31;
                wt[cw * WTS + kw] = fc1w[(j0 + cw) * Cc + k0 + kw];
            }
            __syncthreads();
            unsigned long long wv[16];
            const unsigned long long* wrow = (const unsigned long long*)(wt + gc * WTS);
            #pragma unroll
            for (int p = 0; p < 16; p++) wv[p] = wrow[p];
            #pragma unroll
            for (int rr = 0; rr < 8; rr++) {
                const unsigned long long* ar =
                    (const unsigned long long*)(lnb + (rg + 4 * rr) * Cc + k0);
                #pragma unroll
                for (int p = 0; p < 16; p++) fma2(acc[rr], ar[p], wv[p]);
            }
        }
        int j = j0 + gc;
        float b = fc1b[j];
        #pragma unroll
        for (int rr = 0; rr < 8; rr++) {
            float val = sum2(acc[rr]) + b;
            a1[(rg + 4 * rr) * HID + j] = val * normcdff(val);  // exact GELU
        }
    }
    __syncthreads();

    // ---- fc2: [32,768] @ [768,192]^T + b + residual -> out ----
    for (int j0 = 0; j0 < Cc; j0 += 64) {
        unsigned long long acc[8];
        #pragma unroll
        for (int rr = 0; rr < 8; rr++) acc[rr] = 0ull;
        for (int k0 = 0; k0 < HID; k0 += 32) {
            __syncthreads();
            #pragma unroll
            for (int l = 0; l < 8; l++) {
                int e = tid + l * TPB;
                int cw = e >> 5, kw = e & 31;
                wt[cw * WTS + kw] = fc2w[(j0 + cw) * HID + k0 + kw];
            }
            __syncthreads();
            unsigned long long wv[16];
            const unsigned long long* wrow = (const unsigned long long*)(wt + gc * WTS);
            #pragma unroll
            for (int p = 0; p < 16; p++) wv[p] = wrow[p];
            #pragma unroll
            for (int rr = 0; rr < 8; rr++) {
                const unsigned long long* ar =
                    (const unsigned long long*)(a1 + (rg + 4 * rr) * HID + k0);
                #pragma unroll
                for (int p = 0; p < 16; p++) fma2(acc[rr], ar[p], wv[p]);
            }
        }
        int j = j0 + gc;
        float b = fc2b[j];
        #pragma unroll
        for (int rr = 0; rr < 8; rr++) {
            int n = rg + 4 * rr;
            out[(size_t)(t0 + n) * Cc + j] = ht[n * Cc + j] + sum2(acc[rr]) + b;
        }
    }
}

// =====================================================================
extern "C" void kernel_launch(void* const* d_in, const int* in_sizes, int n_in,
                              void* d_out, int out_size) {
    const float* x     = (const float*)d_in[0];
    const float* n1g   = (const float*)d_in[1];
    const float* n1b   = (const float*)d_in[2];
    const float* qkvw  = (const float*)d_in[3];
    const float* qkvb  = (const float*)d_in[4];
    const float* projw = (const float*)d_in[5];
    const float* projb = (const float*)d_in[6];
    const float* rpbt  = (const float*)d_in[7];
    const float* n2g   = (const float*)d_in[8];
    const float* n2b   = (const float*)d_in[9];
    const float* fc1w  = (const float*)d_in[10];
    const float* fc1b  = (const float*)d_in[11];
    const float* fc2w  = (const float*)d_in[12];
    const float* fc2b  = (const float*)d_in[13];
    float* out = (float*)d_out;

    cudaFuncSetAttribute(attn_kernel, cudaFuncAttributeMaxDynamicSharedMemorySize,
                         SMEM1_W * 4);
    cudaFuncSetAttribute(mlp_kernel, cudaFuncAttributeMaxDynamicSharedMemorySize,
                         SMEM2_W * 4);

    attn_kernel<<<NBLK, TPB, SMEM1_W * 4>>>(x, n1g, n1b, qkvw, qkvb, projw, projb,
                                            rpbt);
    mlp_kernel<<<Tt / 32, TPB, SMEM2_W * 4>>>(n2g, n2b, fc1w, fc1b, fc2w, fc2b, out);
}

// round 2
// speedup vs baseline: 2.6150x; 2.6150x over previous
#include <cuda_runtime.h>
#include <math.h>

// ---------------- problem constants ----------------
namespace cfg {
constexpr int Cc = 192, NHc = 6, Nn = 49;
constexpr int Tt = 100352;           // 32*56*56 tokens
constexpr int HID = 768, QKVN = 576;
constexpr float SCALE = 0.17677669529663689f;   // 1/sqrt(32)
constexpr float EPSc = 1e-5f;
}
using namespace cfg;

// ---------------- scratch (static device allocs) ----------------
__device__ float g_ln1[(size_t)Tt * Cc];
__device__ float g_qkv[(size_t)Tt * QKVN];
__device__ float g_att[(size_t)Tt * Cc];
__device__ float g_h  [(size_t)Tt * Cc];
__device__ float g_ln2[(size_t)Tt * Cc];
__device__ float g_a1 [(size_t)Tt * HID];
__device__ float g_wr [442368];   // rounded weights: qkv|proj|fc1|fc2
// float offsets into g_wr:
constexpr size_t WO_QKV = 0, WO_PROJ = 110592, WO_FC1 = 147456, WO_FC2 = 294912;

// ---------------- helpers ----------------
__device__ __forceinline__ float to_tf32(float x) {
    unsigned int u;
    asm("cvt.rna.tf32.f32 %0, %1;" : "=r"(u) : "f"(x));
    return __uint_as_float(u);
}
__device__ __forceinline__ void cp16(unsigned int s, const void* g) {
    asm volatile("cp.async.cg.shared.global [%0], [%1], 16;" :: "r"(s), "l"(g));
}
__device__ __forceinline__ void cp_commit() {
    asm volatile("cp.async.commit_group;" ::: "memory");
}
template <int N>
__device__ __forceinline__ void cp_wait() {
    asm volatile("cp.async.wait_group %0;" :: "n"(N) : "memory");
}
__device__ __forceinline__ void mma8(float* c, const unsigned int* a,
                                     const unsigned int* b) {
    asm volatile(
        "mma.sync.aligned.m16n8k8.row.col.f32.tf32.tf32.f32 "
        "{%0,%1,%2,%3},{%4,%5,%6,%7},{%8,%9},{%0,%1,%2,%3};"
        : "+f"(c[0]), "+f"(c[1]), "+f"(c[2]), "+f"(c[3])
        : "r"(a[0]), "r"(a[1]), "r"(a[2]), "r"(a[3]), "r"(b[0]), "r"(b[1]));
}
__device__ __forceinline__ void fma2(unsigned long long& d,
                                     unsigned long long a,
                                     unsigned long long b) {
    asm("fma.rn.f32x2 %0, %1, %2, %0;" : "+l"(d) : "l"(a), "l"(b));
}
__device__ __forceinline__ float sum2(unsigned long long a) {
    return __uint_as_float((unsigned int)a) +
           __uint_as_float((unsigned int)(a >> 32));
}

// ---------------- weight tf32 pre-round ----------------
__global__ void round_kernel(const float* __restrict__ src,
                             float* __restrict__ dst, int n4) {
    int i = blockIdx.x * 256 + threadIdx.x;
    if (i < n4) {
        float4 v = ((const float4*)src)[i];
        v.x = to_tf32(v.x); v.y = to_tf32(v.y);
        v.z = to_tf32(v.z); v.w = to_tf32(v.w);
        ((float4*)dst)[i] = v;
    }
}

// ---------------- LayerNorm (one warp per token, tf32-rounded out) -------
__global__ void __launch_bounds__(256, 1)
ln_kernel(const float* __restrict__ src, const float* __restrict__ g,
          const float* __restrict__ b, float* __restrict__ dst) {
    const int wp = threadIdx.x >> 5, lane = threadIdx.x & 31;
    const int t = blockIdx.x * 8 + wp;
    const float* r = src + (size_t)t * Cc;
    float vals[6], s = 0.f;
    #pragma unroll
    for (int j = 0; j < 6; j++) { vals[j] = r[lane + 32 * j]; s += vals[j]; }
    #pragma unroll
    for (int o = 16; o; o >>= 1) s += __shfl_xor_sync(~0u, s, o);
    float mu = s * (1.f / 192.f), s2 = 0.f;
    #pragma unroll
    for (int j = 0; j < 6; j++) { float d = vals[j] - mu; s2 += d * d; }
    #pragma unroll
    for (int o = 16; o; o >>= 1) s2 += __shfl_xor_sync(~0u, s2, o);
    float rs = rsqrtf(s2 * (1.f / 192.f) + EPSc);
    float* w = dst + (size_t)t * Cc;
    #pragma unroll
    for (int j = 0; j < 6; j++) {
        int cc = lane + 32 * j;
        w[cc] = to_tf32((vals[j] - mu) * rs * g[cc] + b[cc]);
    }
}

// ---------------- tf32 tensor-core GEMM ----------------
// C[M,N] = A[M,K] @ B[N,K]^T (+bias, epilogue).  M tile 256, N tile 128,
// 8 warps, warp tile 64x64, K chunks of 32, cp.async double buffer.
// EPI: 0 = qkv (scale cols<192), 1 = residual add, 2 = gelu + tf32 round
constexpr int AS_W = 256 * 36, BS_W = 128 * 36, BUF_W = AS_W + BS_W;
constexpr int GEMM_SMEM = BUF_W * 2 * 4;   // 110592 B

template <int NCOLS, int KDIM, int EPI>
__global__ void __launch_bounds__(256, 1)
gemm_kernel(const float* __restrict__ A, const float* __restrict__ Bw,
            const float* __restrict__ bias, const float* __restrict__ res,
            float* __restrict__ out) {
    extern __shared__ float smem_g[];
    const int tid = threadIdx.x, wid = tid >> 5, lane = tid & 31;
    const int wm = wid >> 1, wn = wid & 1;
    const int n0 = blockIdx.x * 128;
    const int m0 = blockIdx.y * 256;
    constexpr int NC = KDIM / 32;
    const unsigned int sbase = (unsigned int)__cvta_generic_to_shared(smem_g);

    auto stage = [&](int buf, int c) {
        const int k0 = c * 32;
        const unsigned int sa = sbase + (unsigned)(buf * BUF_W) * 4u;
        #pragma unroll
        for (int i = 0; i < 8; i++) {
            int s = tid + i * 256;          // 2048 A segs
            int row = s >> 3, cq = s & 7;
            cp16(sa + (unsigned)(row * 36 + cq * 4) * 4u,
                 A + (size_t)(m0 + row) * KDIM + k0 + cq * 4);
        }
        const unsigned int sb = sbase + (unsigned)(buf * BUF_W + AS_W) * 4u;
        #pragma unroll
        for (int i = 0; i < 4; i++) {
            int s = tid + i * 256;          // 1024 B segs
            int row = s >> 3, cq = s & 7;
            int gn = n0 + row; if (gn > NCOLS - 1) gn = NCOLS - 1;
            cp16(sb + (unsigned)(row * 36 + cq * 4) * 4u,
                 Bw + (size_t)gn * KDIM + k0 + cq * 4);
        }
    };

    float acc[4][8][4];
    #pragma unroll
    for (int mi = 0; mi < 4; mi++)
        #pragma unroll
        for (int ni = 0; ni < 8; ni++)
            #pragma unroll
            for (int q = 0; q < 4; q++) acc[mi][ni][q] = 0.f;

    stage(0, 0); cp_commit();

    const int la = lane >> 2, lb = lane & 3;
    for (int ch = 0; ch < NC; ch++) {
        if (ch + 1 < NC) { stage((ch + 1) & 1, ch + 1); cp_commit(); cp_wait<1>(); }
        else cp_wait<0>();
        __syncthreads();
        const unsigned int* As = (const unsigned int*)(smem_g + (ch & 1) * BUF_W);
        const unsigned int* Bs = As + AS_W;
        #pragma unroll
        for (int kk = 0; kk < 4; kk++) {
            unsigned int a[4][4], b[8][2];
            const int ac = kk * 8 + lb;
            #pragma unroll
            for (int mi = 0; mi < 4; mi++) {
                int base = (wm * 64 + mi * 16 + la) * 36 + ac;
                a[mi][0] = As[base];           a[mi][1] = As[base + 8 * 36];
                a[mi][2] = As[base + 4];       a[mi][3] = As[base + 8 * 36 + 4];
            }
            #pragma unroll
            for (int ni = 0; ni < 8; ni++) {
                int base = (wn * 64 + ni * 8 + la) * 36 + ac;
                b[ni][0] = Bs[base];           b[ni][1] = Bs[base + 4];
            }
            #pragma unroll
            for (int mi = 0; mi < 4; mi++)
                #pragma unroll
                for (int ni = 0; ni < 8; ni++) mma8(acc[mi][ni], a[mi], b[ni]);
        }
        __syncthreads();
    }

    // ---- epilogue ----
    const int er = m0 + wm * 64 + la;
    const int ec = n0 + wn * 64 + lb * 2;
    #pragma unroll
    for (int ni = 0; ni < 8; ni++) {
        const int col = ec + ni * 8;
        if (col < NCOLS) {
            const float b0 = bias[col], b1 = bias[col + 1];
            #pragma unroll
            for (int mi = 0; mi < 4; mi++) {
                const int r0 = er + mi * 16;
                #pragma unroll
                for (int half = 0; half < 2; half++) {
                    const int r = r0 + half * 8;
                    float v0 = acc[mi][ni][half * 2 + 0] + b0;
                    float v1 = acc[mi][ni][half * 2 + 1] + b1;
                    const size_t off = (size_t)r * NCOLS + col;
                    float2 o;
                    if (EPI == 0) {             // qkv: scale q columns
                        if (col < 192) { v0 *= SCALE; v1 *= SCALE; }
                        o.x = v0; o.y = v1;
                    } else if (EPI == 1) {      // residual add
                        float2 rv = *(const float2*)(res + off);
                        o.x = rv.x + v0; o.y = rv.y + v1;
                    } else {                    // exact GELU, tf32 round
                        o.x = to_tf32(v0 * normcdff(v0));
                        o.y = to_tf32(v1 * normcdff(v1));
                    }
                    *(float2*)(out + off) = o;
                }
            }
        }
    }
}

// ---------------- attention (per shifted window) ----------------
// smem float offsets
constexpr int KQS = 34;                        // per-head row stride
constexpr int OQ = 0, OKk = 9996, OV = 19992;  // 6*49*34 each
constexpr int OSC = 29988;                     // 6*49*50
constexpr int ORPB = OSC + 6 * 49 * 50;        // 44688, 169*6
constexpr int OTOK = ORPB + 1014;              // 45702 (49 ints)
constexpr int OLAB = OTOK + 49;                // 45751
constexpr int ATT_SMEM_W = OLAB + 49;          // 45800 words
constexpr int ATT_SMEM = ATT_SMEM_W * 4;       // 183200 B

__global__ void __launch_bounds__(256, 1)
attn_kernel(const float* __restrict__ qkv, const float* __restrict__ rpbt,
            float* __restrict__ att) {
    extern __shared__ float sm[];
    int* tok = (int*)(sm + OTOK);
    int* lab = (int*)(sm + OLAB);
    const int tid = threadIdx.x, wp = tid >> 5, lane = tid & 31;
    const int bw = blockIdx.x, img = bw >> 6, win = bw & 63;
    const int wr = win >> 3, wcw = win & 7;

    if (tid < Nn) {
        int r = tid / 7, c = tid % 7;
        int sy = (wr * 7 + r + 3) % 56, sx = (wcw * 7 + c + 3) % 56;
        tok[tid] = img * 3136 + sy * 56 + sx;
        int y = wr * 7 + r, xx = wcw * 7 + c;
        lab[tid] = ((y < 49) ? 0 : (y < 53 ? 1 : 2)) * 3 +
                   ((xx < 49) ? 0 : (xx < 53 ? 1 : 2));
    }
    for (int i = tid; i < 1014; i += 256) sm[ORPB + i] = rpbt[i];
    __syncthreads();

    // stage q/k/v into per-head layout [sec][h*49+i][34]
    for (int e = tid; e < 49 * 144; e += 256) {
        int i = e / 144, c4 = e - i * 144;
        float4 v = *(const float4*)(qkv + (size_t)tok[i] * QKVN + c4 * 4);
        int sec = c4 / 48, cc = (c4 - sec * 48) * 4;
        int h = cc >> 5, d = cc & 31;
        float* dst = sm + sec * 9996 + (h * 49 + i) * KQS + d;
        dst[0] = v.x; dst[1] = v.y; dst[2] = v.z; dst[3] = v.w;
    }
    __syncthreads();

    // scores + softmax: warp per (i, h)
    for (int task = wp; task < NHc * Nn; task += 8) {
        int h = task / 49, i = task - h * 49;
        const unsigned long long* qp =
            (const unsigned long long*)(sm + OQ + (h * 49 + i) * KQS);
        unsigned long long qr[16];
        #pragma unroll
        for (int p = 0; p < 16; p++) qr[p] = qp[p];
        int ri = i / 7, ci = i % 7, li = lab[i];

        float s0, s1;
        {
            int j = lane;
            const unsigned long long* kp =
                (const unsigned long long*)(sm + OKk + (h * 49 + j) * KQS);
            unsigned long long a = 0ull;
            #pragma unroll
            for (int p = 0; p < 16; p++) fma2(a, qr[p], kp[p]);
            float sv = sum2(a);
            int rj = j / 7, cj = j % 7;
            sv += sm[ORPB + ((ri - rj + 6) * 13 + (ci - cj + 6)) * 6 + h];
            if (lab[j] != li) sv -= 100.f;
            s0 = sv;
        }
        if (lane < 17) {
            int j = lane + 32;
            const unsigned long long* kp =
                (const unsigned long long*)(sm + OKk + (h * 49 + j) * KQS);
            unsigned long long a = 0ull;
            #pragma unroll
            for (int p = 0; p < 16; p++) fma2(a, qr[p], kp[p]);
            float sv = sum2(a);
            int rj = j / 7, cj = j % 7;
            sv += sm[ORPB + ((ri - rj + 6) * 13 + (ci - cj + 6)) * 6 + h];
            if (lab[j] != li) sv -= 100.f;
            s1 = sv;
        } else s1 = __int_as_float(0xff800000);

        float m = fmaxf(s0, s1);
        #pragma unroll
        for (int o = 16; o; o >>= 1) m = fmaxf(m, __shfl_xor_sync(~0u, m, o));
        float e0 = __expf(s0 - m);
        float e1 = (lane < 17) ? __expf(s1 - m) : 0.f;
        float ssum = e0 + e1;
        #pragma unroll
        for (int o = 16; o; o >>= 1) ssum += __shfl_xor_sync(~0u, ssum, o);
        float inv = __frcp_rn(ssum);
        float* scr = sm + OSC + (h * 49 + i) * 50;
        scr[lane] = e0 * inv;
        if (lane < 17) scr[lane + 32] = e1 * inv;
    }
    __syncthreads();

    // P @ V : thread per (i, h, d-pair); scatter to token layout (tf32)
    for (int e = tid; e < Nn * NHc * 16; e += 256) {
        int i = e / 96, rem = e - i * 96;
        int h = rem >> 4, dp = rem & 15;
        const float* vp = sm + OV + (h * 49) * KQS + 2 * dp;
        const float* pp = sm + OSC + (h * 49 + i) * 50;
        float ax = 0.f, ay = 0.f;
        #pragma unroll
        for (int j = 0; j < Nn; j++) {
            float p = pp[j];
            float2 vv = *(const float2*)(vp + j * KQS);
            ax += p * vv.x; ay += p * vv.y;
        }
        float2 o; o.x = to_tf32(ax); o.y = to_tf32(ay);
        *(float2*)(att + (size_t)tok[i] * Cc + h * 32 + 2 * dp) = o;
    }
}

// ---------------- launch ----------------
extern "C" void kernel_launch(void* const* d_in, const int* in_sizes, int n_in,
                              void* d_out, int out_size) {
    const float* x     = (const float*)d_in[0];
    const float* n1g   = (const float*)d_in[1];
    const float* n1b   = (const float*)d_in[2];
    const float* qkvw  = (const float*)d_in[3];
    const float* qkvb  = (const float*)d_in[4];
    const float* projw = (const float*)d_in[5];
    const float* projb = (const float*)d_in[6];
    const float* rpbt  = (const float*)d_in[7];
    const float* n2g   = (const float*)d_in[8];
    const float* n2b   = (const float*)d_in[9];
    const float* fc1w  = (const float*)d_in[10];
    const float* fc1b  = (const float*)d_in[11];
    const float* fc2w  = (const float*)d_in[12];
    const float* fc2b  = (const float*)d_in[13];
    float* out = (float*)d_out;

    float *ln1, *qkvs, *atts, *hs, *ln2, *a1, *wr;
    cudaGetSymbolAddress((void**)&ln1,  g_ln1);
    cudaGetSymbolAddress((void**)&qkvs, g_qkv);
    cudaGetSymbolAddress((void**)&atts, g_att);
    cudaGetSymbolAddress((void**)&hs,   g_h);
    cudaGetSymbolAddress((void**)&ln2,  g_ln2);
    cudaGetSymbolAddress((void**)&a1,   g_a1);
    cudaGetSymbolAddress((void**)&wr,   g_wr);

    cudaFuncSetAttribute(gemm_kernel<QKVN, Cc, 0>,
                         cudaFuncAttributeMaxDynamicSharedMemorySize, GEMM_SMEM);
    cudaFuncSetAttribute(gemm_kernel<Cc, Cc, 1>,
                         cudaFuncAttributeMaxDynamicSharedMemorySize, GEMM_SMEM);
    cudaFuncSetAttribute(gemm_kernel<HID, Cc, 2>,
                         cudaFuncAttributeMaxDynamicSharedMemorySize, GEMM_SMEM);
    cudaFuncSetAttribute(gemm_kernel<Cc, HID, 1>,
                         cudaFuncAttributeMaxDynamicSharedMemorySize, GEMM_SMEM);
    cudaFuncSetAttribute(attn_kernel,
                         cudaFuncAttributeMaxDynamicSharedMemorySize, ATT_SMEM);

    // pre-round weights to tf32
    round_kernel<<<(27648 + 255) / 256, 256>>>(qkvw, wr + WO_QKV, 27648);
    round_kernel<<<(9216  + 255) / 256, 256>>>(projw, wr + WO_PROJ, 9216);
    round_kernel<<<(36864 + 255) / 256, 256>>>(fc1w, wr + WO_FC1, 36864);
    round_kernel<<<(36864 + 255) / 256, 256>>>(fc2w, wr + WO_FC2, 36864);

    ln_kernel<<<Tt / 8, 256>>>(x, n1g, n1b, ln1);
    gemm_kernel<QKVN, Cc, 0><<<dim3(5, 392), 256, GEMM_SMEM>>>(
        ln1, wr + WO_QKV, qkvb, nullptr, qkvs);
    attn_kernel<<<2048, 256, ATT_SMEM>>>(qkvs, rpbt, atts);
    gemm_kernel<Cc, Cc, 1><<<dim3(2, 392), 256, GEMM_SMEM>>>(
        atts, wr + WO_PROJ, projb, x, hs);
    ln_kernel<<<Tt / 8, 256>>>(hs, n2g, n2b, ln2);
    gemm_kernel<HID, Cc, 2><<<dim3(6, 392), 256, GEMM_SMEM>>>(
        ln2, wr + WO_FC1, fc1b, nullptr, a1);
    gemm_kernel<Cc, HID, 1><<<dim3(2, 392), 256, GEMM_SMEM>>>(
        a1, wr + WO_FC2, fc2b, hs, out);
}